// round 1
// baseline (speedup 1.0000x reference)
#include <cuda_runtime.h>
#include <cuda_bf16.h>

// Problem dims (fixed by the reference)
#define BATCH 4
#define SEQ   2048
#define EMBED 1024
#define HID   4096
#define VOCAB 32000

// ---------------------------------------------------------------------------
// Scratch (device globals; allocation inside kernel_launch is forbidden)
// ---------------------------------------------------------------------------
__device__ float g_x[BATCH * SEQ * EMBED];       // 33.5 MB  embedded tokens
__device__ float g_scores[BATCH * SEQ * SEQ];    // 67  MB  attention scores/weights (in-place softmax)
__device__ float g_att[BATCH * SEQ * EMBED];     // 33.5 MB  attended
__device__ float g_hidden[BATCH * SEQ * HID];    // 134 MB  FFN1 output

// ---------------------------------------------------------------------------
// Embedding gather: x[r, :] = emb[ids[r], :]   (r = 0..BATCH*SEQ-1)
// One block per row; 256 threads x float4 = 1024 floats.
// ---------------------------------------------------------------------------
__global__ void embed_kernel(const int* __restrict__ ids,
                             const float* __restrict__ emb,
                             float* __restrict__ x) {
    int row = blockIdx.x;
    int id  = ids[row];
    const float4* src = reinterpret_cast<const float4*>(emb + (long)id * EMBED);
    float4*       dst = reinterpret_cast<float4*>(x + (long)row * EMBED);
    dst[threadIdx.x] = src[threadIdx.x];
}

// ---------------------------------------------------------------------------
// Tiled SGEMM: C = A(MxK) * B + bias, optional ReLU.
// TRANSB=false: B is KxN row-major.  TRANSB=true: B is NxK row-major (C=A*B^T).
// BM=BN=128, BK=16, 256 threads, 8x8 register tile per thread.
// All dims assumed divisible by the tile sizes (true for this problem).
// blockIdx.z = batch (with element strides sA/sB/sC).
// ---------------------------------------------------------------------------
template<bool TRANSB, bool BIAS, bool RELU>
__global__ __launch_bounds__(256)
void sgemm_kernel(const float* __restrict__ A,
                  const float* __restrict__ B,
                  const float* __restrict__ bias,
                  float* __restrict__ C,
                  int M, int N, int K,
                  long sA, long sB, long sC) {
    constexpr int BM = 128, BN = 128, BK = 16, TM = 8, TN = 8;

    A += (long)blockIdx.z * sA;
    B += (long)blockIdx.z * sB;
    C += (long)blockIdx.z * sC;

    __shared__ float As[BK][BM];       // stored transposed: As[k][m]
    __shared__ float Bs[BK][BN];       // Bs[k][n]

    const int tid  = threadIdx.x;
    const int trow = tid / (BN / TN);  // 0..15
    const int tcol = tid % (BN / TN);  // 0..15

    const int m0 = blockIdx.y * BM;
    const int n0 = blockIdx.x * BN;

    // A-load indexing: 128 rows x 4 float4 per row, 2 sweeps of 64 rows
    const int a_r = tid >> 2;          // 0..63
    const int a_c = (tid & 3) * 4;     // 0,4,8,12

    // B-load indexing (NN): 16 rows x 32 float4 per row, 2 sweeps of 8 rows
    const int b_r = tid >> 5;          // 0..7
    const int b_c = (tid & 31) * 4;    // 0..124

    float acc[TM][TN];
    #pragma unroll
    for (int i = 0; i < TM; i++)
        #pragma unroll
        for (int j = 0; j < TN; j++) acc[i][j] = 0.f;

    for (int kt = 0; kt < K; kt += BK) {
        // ---- load A tile (transpose into As[k][m]) ----
        #pragma unroll
        for (int s = 0; s < 2; s++) {
            int r = a_r + s * 64;
            float4 v = *reinterpret_cast<const float4*>(&A[(long)(m0 + r) * K + kt + a_c]);
            As[a_c + 0][r] = v.x;
            As[a_c + 1][r] = v.y;
            As[a_c + 2][r] = v.z;
            As[a_c + 3][r] = v.w;
        }
        // ---- load B tile ----
        if (!TRANSB) {
            #pragma unroll
            for (int s = 0; s < 2; s++) {
                int r = b_r + s * 8;   // k within tile
                float4 v = *reinterpret_cast<const float4*>(&B[(long)(kt + r) * N + n0 + b_c]);
                *reinterpret_cast<float4*>(&Bs[r][b_c]) = v;
            }
        } else {
            #pragma unroll
            for (int s = 0; s < 2; s++) {
                int r = a_r + s * 64;  // n within tile
                float4 v = *reinterpret_cast<const float4*>(&B[(long)(n0 + r) * K + kt + a_c]);
                Bs[a_c + 0][r] = v.x;
                Bs[a_c + 1][r] = v.y;
                Bs[a_c + 2][r] = v.z;
                Bs[a_c + 3][r] = v.w;
            }
        }
        __syncthreads();

        // ---- compute ----
        #pragma unroll
        for (int k = 0; k < BK; k++) {
            float a[TM], b[TN];
            #pragma unroll
            for (int i = 0; i < TM; i++) a[i] = As[k][trow * TM + i];
            #pragma unroll
            for (int j = 0; j < TN; j++) b[j] = Bs[k][tcol * TN + j];
            #pragma unroll
            for (int i = 0; i < TM; i++)
                #pragma unroll
                for (int j = 0; j < TN; j++)
                    acc[i][j] = fmaf(a[i], b[j], acc[i][j]);
        }
        __syncthreads();
    }

    // ---- epilogue ----
    const int crow = m0 + trow * TM;
    const int ccol = n0 + tcol * TN;
    float bv[TN];
    if (BIAS) {
        #pragma unroll
        for (int j = 0; j < TN; j++) bv[j] = bias[ccol + j];
    }
    #pragma unroll
    for (int i = 0; i < TM; i++) {
        #pragma unroll
        for (int j = 0; j < TN; j += 4) {
            float4 v;
            v.x = acc[i][j + 0]; v.y = acc[i][j + 1];
            v.z = acc[i][j + 2]; v.w = acc[i][j + 3];
            if (BIAS) { v.x += bv[j]; v.y += bv[j + 1]; v.z += bv[j + 2]; v.w += bv[j + 3]; }
            if (RELU) {
                v.x = fmaxf(v.x, 0.f); v.y = fmaxf(v.y, 0.f);
                v.z = fmaxf(v.z, 0.f); v.w = fmaxf(v.w, 0.f);
            }
            *reinterpret_cast<float4*>(&C[(long)(crow + i) * N + ccol + j]) = v;
        }
    }
}

// ---------------------------------------------------------------------------
// Row softmax, in place. One block (256 thr) per row of length SEQ=2048.
// ---------------------------------------------------------------------------
__global__ __launch_bounds__(256)
void softmax_kernel(float* __restrict__ scores) {
    __shared__ float red[256];
    float* row = scores + (long)blockIdx.x * SEQ;
    const int tid = threadIdx.x;

    float v[8];
    float lmax = -3.402823466e+38f;
    #pragma unroll
    for (int i = 0; i < 8; i++) {
        v[i] = row[tid + i * 256];
        lmax = fmaxf(lmax, v[i]);
    }
    red[tid] = lmax;
    __syncthreads();
    #pragma unroll
    for (int s = 128; s > 0; s >>= 1) {
        if (tid < s) red[tid] = fmaxf(red[tid], red[tid + s]);
        __syncthreads();
    }
    float m = red[0];
    __syncthreads();

    float lsum = 0.f;
    #pragma unroll
    for (int i = 0; i < 8; i++) {
        v[i] = __expf(v[i] - m);
        lsum += v[i];
    }
    red[tid] = lsum;
    __syncthreads();
    #pragma unroll
    for (int s = 128; s > 0; s >>= 1) {
        if (tid < s) red[tid] += red[tid + s];
        __syncthreads();
    }
    float inv = 1.f / red[0];
    #pragma unroll
    for (int i = 0; i < 8; i++) row[tid + i * 256] = v[i] * inv;
}

// ---------------------------------------------------------------------------
// Launch
// ---------------------------------------------------------------------------
extern "C" void kernel_launch(void* const* d_in, const int* in_sizes, int n_in,
                              void* d_out, int out_size) {
    const int*   ids = (const int*)  d_in[0];   // [4,2048]
    const float* emb = (const float*)d_in[1];   // [32000,1024]
    const float* W1  = (const float*)d_in[2];   // [1024,4096]
    const float* b1  = (const float*)d_in[3];   // [4096]
    const float* W2  = (const float*)d_in[4];   // [4096,32000]
    const float* b2  = (const float*)d_in[5];   // [32000]
    float* out = (float*)d_out;                 // [4,2048,32000]

    float* x      = nullptr;
    float* scores = nullptr;
    float* att    = nullptr;
    float* hidden = nullptr;
    cudaGetSymbolAddress((void**)&x,      g_x);
    cudaGetSymbolAddress((void**)&scores, g_scores);
    cudaGetSymbolAddress((void**)&att,    g_att);
    cudaGetSymbolAddress((void**)&hidden, g_hidden);

    // 1) Embedding gather
    embed_kernel<<<BATCH * SEQ, 256>>>(ids, emb, x);

    // 2) scores[b] = x[b] @ x[b]^T   (M=N=2048, K=1024, NT)
    {
        dim3 grid(SEQ / 128, SEQ / 128, BATCH);
        sgemm_kernel<true, false, false><<<grid, 256>>>(
            x, x, nullptr, scores, SEQ, SEQ, EMBED,
            (long)SEQ * EMBED, (long)SEQ * EMBED, (long)SEQ * SEQ);
    }

    // 3) softmax rows
    softmax_kernel<<<BATCH * SEQ, 256>>>(scores);

    // 4) att[b] = weights[b] @ x[b]   (M=2048, N=1024, K=2048, NN)
    {
        dim3 grid(EMBED / 128, SEQ / 128, BATCH);
        sgemm_kernel<false, false, false><<<grid, 256>>>(
            scores, x, nullptr, att, SEQ, EMBED, SEQ,
            (long)SEQ * SEQ, (long)SEQ * EMBED, (long)SEQ * EMBED);
    }

    // 5) hidden = relu(att @ W1 + b1)   (M=8192, N=4096, K=1024)
    {
        dim3 grid(HID / 128, (BATCH * SEQ) / 128, 1);
        sgemm_kernel<false, true, true><<<grid, 256>>>(
            att, W1, b1, hidden, BATCH * SEQ, HID, EMBED, 0, 0, 0);
    }

    // 6) logits = hidden @ W2 + b2   (M=8192, N=32000, K=4096)
    {
        dim3 grid(VOCAB / 128, (BATCH * SEQ) / 128, 1);
        sgemm_kernel<false, true, false><<<grid, 256>>>(
            hidden, W2, b2, out, BATCH * SEQ, VOCAB, HID, 0, 0, 0);
    }
}

// round 4
// speedup vs baseline: 3.9531x; 3.9531x over previous
#include <cuda_runtime.h>
#include <cuda_fp16.h>
#include <cstdint>

// Problem dims
#define BATCH 4
#define SEQ   2048
#define EMBED 1024
#define HID   4096
#define VOCAB 32000

// ---------------------------------------------------------------------------
// PTX helpers (plain sm_103-legal: cp.async / ldmatrix / mma.sync only)
// ---------------------------------------------------------------------------
__device__ __forceinline__ uint32_t smem_u32(const void* p) {
    uint32_t a;
    asm("{ .reg .u64 t; cvta.to.shared.u64 t, %1; cvt.u32.u64 %0, t; }" : "=r"(a) : "l"(p));
    return a;
}
#define CP_ASYNC16(s, g) \
    asm volatile("cp.async.cg.shared.global [%0], [%1], 16;\n" :: "r"(s), "l"(g))
#define CP_COMMIT() asm volatile("cp.async.commit_group;\n" ::: "memory")
#define CP_WAIT1()  asm volatile("cp.async.wait_group 1;\n" ::: "memory")

__device__ __forceinline__ void ldsm4(uint32_t* r, uint32_t a) {
    asm volatile("ldmatrix.sync.aligned.m8n8.x4.shared.b16 {%0,%1,%2,%3}, [%4];"
        : "=r"(r[0]), "=r"(r[1]), "=r"(r[2]), "=r"(r[3]) : "r"(a));
}
__device__ __forceinline__ void mma16816(float* c, const uint32_t* a, const uint32_t* b) {
    asm volatile(
        "mma.sync.aligned.m16n8k16.row.col.f32.f16.f16.f32 "
        "{%0,%1,%2,%3}, {%4,%5,%6,%7}, {%8,%9}, {%0,%1,%2,%3};"
        : "+f"(c[0]), "+f"(c[1]), "+f"(c[2]), "+f"(c[3])
        : "r"(a[0]), "r"(a[1]), "r"(a[2]), "r"(a[3]), "r"(b[0]), "r"(b[1]));
}

// fp16 hi/lo split (hi+lo covers ~22 mantissa bits of the fp32 value)
__device__ __forceinline__ void hsplit(float v, __half& h, __half& l) {
    h = __float2half_rn(v);
    l = __float2half_rn(v - __half2float(h));
}

// ---------------------------------------------------------------------------
// Scratch (device globals)
// ---------------------------------------------------------------------------
__device__ float  g_x     [BATCH * SEQ * EMBED];
__device__ __half g_xhi   [BATCH * SEQ * EMBED];
__device__ __half g_xlo   [BATCH * SEQ * EMBED];
__device__ __half g_xThi  [BATCH * EMBED * SEQ];
__device__ __half g_xTlo  [BATCH * EMBED * SEQ];
__device__ float  g_scores[BATCH * SEQ * SEQ];
__device__ __half g_whi   [BATCH * SEQ * SEQ];
__device__ __half g_wlo   [BATCH * SEQ * SEQ];
__device__ __half g_atthi [BATCH * SEQ * EMBED];
__device__ __half g_attlo [BATCH * SEQ * EMBED];
__device__ __half g_hidhi [BATCH * SEQ * HID];
__device__ __half g_hidlo [BATCH * SEQ * HID];
__device__ __half g_W1t   [HID * EMBED];
__device__ __half g_W2t   [(size_t)VOCAB * HID];

// ---------------------------------------------------------------------------
// Embedding gather: x fp32 + fp16 hi/lo
// ---------------------------------------------------------------------------
__global__ void embed_kernel(const int* __restrict__ ids, const float* __restrict__ emb,
                             float* __restrict__ x,
                             __half* __restrict__ xhi, __half* __restrict__ xlo) {
    int row = blockIdx.x;
    int id  = ids[row];
    int t = threadIdx.x;
    float4 v = reinterpret_cast<const float4*>(emb + (long)id * EMBED)[t];
    reinterpret_cast<float4*>(x + (long)row * EMBED)[t] = v;
    __half h0, l0, h1, l1, h2, l2, h3, l3;
    hsplit(v.x, h0, l0); hsplit(v.y, h1, l1); hsplit(v.z, h2, l2); hsplit(v.w, h3, l3);
    __half2* dh = reinterpret_cast<__half2*>(xhi + (long)row * EMBED) + t * 2;
    __half2* dl = reinterpret_cast<__half2*>(xlo + (long)row * EMBED) + t * 2;
    dh[0] = __halves2half2(h0, h1); dh[1] = __halves2half2(h2, h3);
    dl[0] = __halves2half2(l0, l1); dl[1] = __halves2half2(l2, l3);
}

// ---------------------------------------------------------------------------
// Transpose fp32 [R,C] -> fp16 [C,R] (hi or hi+lo), batched via z
// ---------------------------------------------------------------------------
template<bool SPLIT>
__global__ void transpose_kernel(const float* __restrict__ in,
                                 __half* __restrict__ ohi, __half* __restrict__ olo,
                                 int R, int C, long sIn, long sOut) {
    __shared__ float t[32][33];
    long z = blockIdx.z;
    in  += z * sIn;
    ohi += z * sOut;
    if (SPLIT) olo += z * sOut;
    int c0 = blockIdx.x * 32, r0 = blockIdx.y * 32;
    int tx = threadIdx.x, ty = threadIdx.y;
    #pragma unroll
    for (int i = 0; i < 32; i += 8)
        t[ty + i][tx] = in[(long)(r0 + ty + i) * C + c0 + tx];
    __syncthreads();
    #pragma unroll
    for (int i = 0; i < 32; i += 8) {
        float v = t[tx][ty + i];
        long o = (long)(c0 + ty + i) * R + r0 + tx;
        if (SPLIT) {
            __half h, l; hsplit(v, h, l);
            ohi[o] = h; olo[o] = l;
        } else {
            ohi[o] = __float2half_rn(v);
        }
    }
}

// ---------------------------------------------------------------------------
// Softmax rows (fp32 in) -> fp16 hi/lo weights
// ---------------------------------------------------------------------------
__global__ __launch_bounds__(256)
void softmax_kernel(const float* __restrict__ scores,
                    __half* __restrict__ whi, __half* __restrict__ wlo) {
    __shared__ float red[256];
    const float* row = scores + (long)blockIdx.x * SEQ;
    __half* oh = whi + (long)blockIdx.x * SEQ;
    __half* ol = wlo + (long)blockIdx.x * SEQ;
    const int tid = threadIdx.x;

    float v[8];
    float lmax = -3.402823466e+38f;
    #pragma unroll
    for (int i = 0; i < 8; i++) { v[i] = row[tid + i * 256]; lmax = fmaxf(lmax, v[i]); }
    red[tid] = lmax; __syncthreads();
    #pragma unroll
    for (int s = 128; s > 0; s >>= 1) { if (tid < s) red[tid] = fmaxf(red[tid], red[tid + s]); __syncthreads(); }
    float m = red[0]; __syncthreads();

    float lsum = 0.f;
    #pragma unroll
    for (int i = 0; i < 8; i++) { v[i] = __expf(v[i] - m); lsum += v[i]; }
    red[tid] = lsum; __syncthreads();
    #pragma unroll
    for (int s = 128; s > 0; s >>= 1) { if (tid < s) red[tid] += red[tid + s]; __syncthreads(); }
    float inv = 1.f / red[0];
    #pragma unroll
    for (int i = 0; i < 8; i++) {
        float w = v[i] * inv;
        __half h, l; hsplit(w, h, l);
        oh[tid + i * 256] = h; ol[tid + i * 256] = l;
    }
}

// ---------------------------------------------------------------------------
// HMMA split-fp16 GEMM:  C[M,N] = A[M,K] * B[N,K]^T
// MODE=2: terms A0*B0 + A1*B0 (A split hi/lo, B single)
// MODE=3: terms A0*B0 + A1*B0 + A0*B1 (A and B both split)
// OUT=0: fp32 (+bias,+relu)   OUT=2: fp16 hi/lo (+bias,+relu)
// CTA 128x128, BK=32, 8 warps (2x4), warp tile 64x32, 3-stage cp.async.
// All dims divisible by tiles (true here). blockIdx.z = batch.
// ---------------------------------------------------------------------------
#define BMT 128
#define BNT 128
#define BKT 32
#define NSTAGE 3
#define TILE_BYTES 8192

template<int TPS>
__device__ __forceinline__ void load_chunk(uint32_t sbase, int st,
    const __half* __restrict__ gA0, const __half* __restrict__ gA1,
    const __half* __restrict__ gB0, const __half* __restrict__ gB1,
    int K, int k0, int tid)
{
    uint32_t s0 = sbase + (uint32_t)(st * TPS * TILE_BYTES);
    #pragma unroll
    for (int it = 0; it < 2; it++) {
        int idx = tid + it * 256;
        int r = idx >> 2, c = idx & 3;
        uint32_t so = (uint32_t)(r * 64 + ((c ^ (r & 3)) << 4));
        long go = (long)r * K + k0 + c * 8;
        CP_ASYNC16(s0 + 0 * TILE_BYTES + so, gA0 + go);
        CP_ASYNC16(s0 + 1 * TILE_BYTES + so, gA1 + go);
        CP_ASYNC16(s0 + 2 * TILE_BYTES + so, gB0 + go);
        if (TPS == 4) CP_ASYNC16(s0 + 3 * TILE_BYTES + so, gB1 + go);
    }
}

template<int MODE, int OUT, bool BIAS, bool RELU>
__global__ __launch_bounds__(256)
void hgemm(const __half* __restrict__ A0, const __half* __restrict__ A1,
           const __half* __restrict__ B0, const __half* __restrict__ B1,
           const float* __restrict__ bias,
           float* __restrict__ Cf, __half* __restrict__ Chi, __half* __restrict__ Clo,
           int M, int N, int K, long sA, long sB, long sC, int ntm)
{
    extern __shared__ char smem[];
    const uint32_t sbase = smem_u32(smem);
    const int tid  = threadIdx.x;
    const int wid  = tid >> 5, lane = tid & 31;
    const int wm   = wid & 1,  wn   = wid >> 1;
    constexpr int TPS = (MODE == 3) ? 4 : 3;

    // n-major CTA order: B column tiles shared via L2 across the M sweep
    int pm = blockIdx.x % ntm, pn = blockIdx.x / ntm;
    long m0 = (long)pm * BMT, n0 = (long)pn * BNT;
    long zb = blockIdx.z;
    const __half* gA0 = A0 + zb * sA + m0 * K;
    const __half* gA1 = A1 + zb * sA + m0 * K;
    const __half* gB0 = B0 + zb * sB + n0 * K;
    const __half* gB1 = (MODE == 3) ? (B1 + zb * sB + n0 * K) : gB0;

    float acc[4][4][4];
    #pragma unroll
    for (int i = 0; i < 4; i++)
        #pragma unroll
        for (int j = 0; j < 4; j++)
            #pragma unroll
            for (int k = 0; k < 4; k++) acc[i][j][k] = 0.f;

    load_chunk<TPS>(sbase, 0, gA0, gA1, gB0, gB1, K, 0, tid);   CP_COMMIT();
    load_chunk<TPS>(sbase, 1, gA0, gA1, gB0, gB1, K, BKT, tid); CP_COMMIT();

    const int nc = K / BKT;
    for (int c = 0; c < nc; c++) {
        CP_WAIT1();
        __syncthreads();
        if (c + 2 < nc)
            load_chunk<TPS>(sbase, (c + 2) % NSTAGE, gA0, gA1, gB0, gB1, K, (c + 2) * BKT, tid);
        CP_COMMIT();

        uint32_t s0 = sbase + (uint32_t)((c % NSTAGE) * TPS * TILE_BYTES);
        #pragma unroll
        for (int kb = 0; kb < BKT; kb += 16) {
            uint32_t a0f[4][4], a1f[4][4], b0f[2][4], b1f[2][4];
            int ar  = lane & 15;
            int akk = kb + ((lane >> 4) << 3);
            int br  = ((lane >> 4) << 3) + (lane & 7);
            int bkk = kb + (((lane >> 3) & 1) << 3);
            #pragma unroll
            for (int mt = 0; mt < 4; mt++) {
                int r = wm * 64 + mt * 16 + ar;
                uint32_t ad = s0 + (uint32_t)(r * 64 + ((((akk >> 3) ^ (r & 3))) << 4));
                ldsm4(a0f[mt], ad);
                ldsm4(a1f[mt], ad + TILE_BYTES);
            }
            #pragma unroll
            for (int nt = 0; nt < 2; nt++) {
                int r = wn * 32 + nt * 16 + br;
                uint32_t bd = s0 + 2 * TILE_BYTES
                            + (uint32_t)(r * 64 + ((((bkk >> 3) ^ (r & 3))) << 4));
                ldsm4(b0f[nt], bd);
                if (MODE == 3) ldsm4(b1f[nt], bd + TILE_BYTES);
            }
            #pragma unroll
            for (int mt = 0; mt < 4; mt++)
                #pragma unroll
                for (int n8 = 0; n8 < 4; n8++) {
                    const uint32_t* b = &b0f[n8 >> 1][(n8 & 1) * 2];
                    mma16816(acc[mt][n8], a0f[mt], b);
                    mma16816(acc[mt][n8], a1f[mt], b);
                    if (MODE == 3)
                        mma16816(acc[mt][n8], a0f[mt], &b1f[n8 >> 1][(n8 & 1) * 2]);
                }
        }
    }

    // ---- epilogue: c-frag direct stores (8B per thread-pair) ----
    long zC = zb * sC;
    int rb = lane >> 2;
    int cb = (lane & 3) * 2;
    #pragma unroll
    for (int mt = 0; mt < 4; mt++) {
        #pragma unroll
        for (int n8 = 0; n8 < 4; n8++) {
            long col = n0 + wn * 32 + n8 * 8 + cb;
            float bv0 = 0.f, bv1 = 0.f;
            if (BIAS) { bv0 = bias[col]; bv1 = bias[col + 1]; }
            #pragma unroll
            for (int h = 0; h < 2; h++) {
                long row = m0 + wm * 64 + mt * 16 + rb + h * 8;
                float v0 = acc[mt][n8][h * 2 + 0] + bv0;
                float v1 = acc[mt][n8][h * 2 + 1] + bv1;
                if (RELU) { v0 = fmaxf(v0, 0.f); v1 = fmaxf(v1, 0.f); }
                long o = row * (long)N + col;
                if (OUT == 0) {
                    *reinterpret_cast<float2*>(Cf + zC + o) = make_float2(v0, v1);
                } else {
                    __half h0, l0, h1, l1;
                    hsplit(v0, h0, l0); hsplit(v1, h1, l1);
                    *reinterpret_cast<__half2*>(Chi + zC + o) = __halves2half2(h0, h1);
                    *reinterpret_cast<__half2*>(Clo + zC + o) = __halves2half2(l0, l1);
                }
            }
        }
    }
}

// ---------------------------------------------------------------------------
// Launch
// ---------------------------------------------------------------------------
extern "C" void kernel_launch(void* const* d_in, const int* in_sizes, int n_in,
                              void* d_out, int out_size) {
    const int*   ids = (const int*)  d_in[0];
    const float* emb = (const float*)d_in[1];
    const float* W1  = (const float*)d_in[2];
    const float* b1  = (const float*)d_in[3];
    const float* W2  = (const float*)d_in[4];
    const float* b2  = (const float*)d_in[5];
    float* out = (float*)d_out;

    float *x, *scores;
    __half *xhi, *xlo, *xThi, *xTlo, *whi, *wlo, *athi, *atlo, *hdhi, *hdlo, *w1t, *w2t;
    cudaGetSymbolAddress((void**)&x,      g_x);
    cudaGetSymbolAddress((void**)&scores, g_scores);
    cudaGetSymbolAddress((void**)&xhi,    g_xhi);
    cudaGetSymbolAddress((void**)&xlo,    g_xlo);
    cudaGetSymbolAddress((void**)&xThi,   g_xThi);
    cudaGetSymbolAddress((void**)&xTlo,   g_xTlo);
    cudaGetSymbolAddress((void**)&whi,    g_whi);
    cudaGetSymbolAddress((void**)&wlo,    g_wlo);
    cudaGetSymbolAddress((void**)&athi,   g_atthi);
    cudaGetSymbolAddress((void**)&atlo,   g_attlo);
    cudaGetSymbolAddress((void**)&hdhi,   g_hidhi);
    cudaGetSymbolAddress((void**)&hdlo,   g_hidlo);
    cudaGetSymbolAddress((void**)&w1t,    g_W1t);
    cudaGetSymbolAddress((void**)&w2t,    g_W2t);

    const int SM3 = 4 * NSTAGE * TILE_BYTES;  // 98304
    const int SM2 = 3 * NSTAGE * TILE_BYTES;  // 73728
    cudaFuncSetAttribute(hgemm<3, 0, false, false>, cudaFuncAttributeMaxDynamicSharedMemorySize, SM3);
    cudaFuncSetAttribute(hgemm<3, 2, false, false>, cudaFuncAttributeMaxDynamicSharedMemorySize, SM3);
    cudaFuncSetAttribute(hgemm<2, 2, true,  true >, cudaFuncAttributeMaxDynamicSharedMemorySize, SM2);
    cudaFuncSetAttribute(hgemm<2, 0, true,  false>, cudaFuncAttributeMaxDynamicSharedMemorySize, SM2);

    // 1) embedding -> x fp32, x hi/lo fp16
    embed_kernel<<<BATCH * SEQ, 256>>>(ids, emb, x, xhi, xlo);

    // 2) xT hi/lo ([S,E] -> [E,S] per batch)
    {
        dim3 grid(EMBED / 32, SEQ / 32, BATCH);
        transpose_kernel<true><<<grid, dim3(32, 8)>>>(x, xThi, xTlo, SEQ, EMBED,
                                                      (long)SEQ * EMBED, (long)EMBED * SEQ);
    }
    // 3) W1t single fp16 ([E,H] -> [H,E])
    {
        dim3 grid(HID / 32, EMBED / 32, 1);
        transpose_kernel<false><<<grid, dim3(32, 8)>>>(W1, w1t, nullptr, EMBED, HID, 0, 0);
    }
    // 4) W2t single fp16 ([H,V] -> [V,H])
    {
        dim3 grid(VOCAB / 32, HID / 32, 1);
        transpose_kernel<false><<<grid, dim3(32, 8)>>>(W2, w2t, nullptr, HID, VOCAB, 0, 0);
    }

    // 5) scores = x @ x^T   (3-term, fp32 out)  M=N=2048 K=1024
    {
        dim3 grid((SEQ / BMT) * (SEQ / BNT), 1, BATCH);
        hgemm<3, 0, false, false><<<grid, 256, SM3>>>(
            xhi, xlo, xhi, xlo, nullptr, scores, nullptr, nullptr,
            SEQ, SEQ, EMBED, (long)SEQ * EMBED, (long)SEQ * EMBED, (long)SEQ * SEQ,
            SEQ / BMT);
    }

    // 6) softmax -> w hi/lo
    softmax_kernel<<<BATCH * SEQ, 256>>>(scores, whi, wlo);

    // 7) attended = w @ x   (3-term, fp16 hi/lo out)  M=2048 N=1024 K=2048
    {
        dim3 grid((SEQ / BMT) * (EMBED / BNT), 1, BATCH);
        hgemm<3, 2, false, false><<<grid, 256, SM3>>>(
            whi, wlo, xThi, xTlo, nullptr, nullptr, athi, atlo,
            SEQ, EMBED, SEQ, (long)SEQ * SEQ, (long)EMBED * SEQ, (long)SEQ * EMBED,
            SEQ / BMT);
    }

    // 8) hidden = relu(att @ W1 + b1)  (2-term A-split, fp16 hi/lo out)  M=8192 N=4096 K=1024
    {
        dim3 grid(((BATCH * SEQ) / BMT) * (HID / BNT), 1, 1);
        hgemm<2, 2, true, true><<<grid, 256, SM2>>>(
            athi, atlo, w1t, nullptr, b1, nullptr, hdhi, hdlo,
            BATCH * SEQ, HID, EMBED, 0, 0, 0,
            (BATCH * SEQ) / BMT);
    }

    // 9) logits = hidden @ W2 + b2  (2-term A-split, fp32 out)  M=8192 N=32000 K=4096
    {
        dim3 grid(((BATCH * SEQ) / BMT) * (VOCAB / BNT), 1, 1);
        hgemm<2, 0, true, false><<<grid, 256, SM2>>>(
            hdhi, hdlo, w2t, nullptr, b2, out, nullptr, nullptr,
            BATCH * SEQ, VOCAB, HID, 0, 0, 0,
            (BATCH * SEQ) / BMT);
    }
}

// round 5
// speedup vs baseline: 5.9726x; 1.5109x over previous
#include <cuda_runtime.h>
#include <cuda_fp16.h>
#include <cstdint>

// Problem dims
#define BATCH 4
#define SEQ   2048
#define EMBED 1024
#define HID   4096
#define VOCAB 32000

// ---------------------------------------------------------------------------
// PTX helpers (plain sm_103-legal: cp.async / ldmatrix / mma.sync only)
// ---------------------------------------------------------------------------
__device__ __forceinline__ uint32_t smem_u32(const void* p) {
    uint32_t a;
    asm("{ .reg .u64 t; cvta.to.shared.u64 t, %1; cvt.u32.u64 %0, t; }" : "=r"(a) : "l"(p));
    return a;
}
#define CP_ASYNC16(s, g) \
    asm volatile("cp.async.cg.shared.global [%0], [%1], 16;\n" :: "r"(s), "l"(g))
#define CP_COMMIT() asm volatile("cp.async.commit_group;\n" ::: "memory")
#define CP_WAIT1()  asm volatile("cp.async.wait_group 1;\n" ::: "memory")
#define CP_WAIT2()  asm volatile("cp.async.wait_group 2;\n" ::: "memory")

__device__ __forceinline__ void ldsm4(uint32_t* r, uint32_t a) {
    asm volatile("ldmatrix.sync.aligned.m8n8.x4.shared.b16 {%0,%1,%2,%3}, [%4];"
        : "=r"(r[0]), "=r"(r[1]), "=r"(r[2]), "=r"(r[3]) : "r"(a));
}
__device__ __forceinline__ void mma16816(float* c, const uint32_t* a, const uint32_t* b) {
    asm volatile(
        "mma.sync.aligned.m16n8k16.row.col.f32.f16.f16.f32 "
        "{%0,%1,%2,%3}, {%4,%5,%6,%7}, {%8,%9}, {%0,%1,%2,%3};"
        : "+f"(c[0]), "+f"(c[1]), "+f"(c[2]), "+f"(c[3])
        : "r"(a[0]), "r"(a[1]), "r"(a[2]), "r"(a[3]), "r"(b[0]), "r"(b[1]));
}

// fp16 hi/lo split (hi+lo covers ~22 mantissa bits of the fp32 value)
__device__ __forceinline__ void hsplit(float v, __half& h, __half& l) {
    h = __float2half_rn(v);
    l = __float2half_rn(v - __half2float(h));
}

// ---------------------------------------------------------------------------
// Scratch (device globals)
// ---------------------------------------------------------------------------
__device__ float  g_x     [BATCH * SEQ * EMBED];
__device__ __half g_xhi   [BATCH * SEQ * EMBED];
__device__ __half g_xlo   [BATCH * SEQ * EMBED];
__device__ __half g_xThi  [BATCH * EMBED * SEQ];
__device__ __half g_xTlo  [BATCH * EMBED * SEQ];
__device__ float  g_scores[BATCH * SEQ * SEQ];
__device__ __half g_whi   [BATCH * SEQ * SEQ];
__device__ __half g_wlo   [BATCH * SEQ * SEQ];
__device__ __half g_atthi [BATCH * SEQ * EMBED];
__device__ __half g_attlo [BATCH * SEQ * EMBED];
__device__ __half g_hidhi [BATCH * SEQ * HID];
__device__ __half g_W1t   [HID * EMBED];
__device__ __half g_W2t   [(size_t)VOCAB * HID];

// ---------------------------------------------------------------------------
// Embedding gather: x fp32 + fp16 hi/lo
// ---------------------------------------------------------------------------
__global__ void embed_kernel(const int* __restrict__ ids, const float* __restrict__ emb,
                             float* __restrict__ x,
                             __half* __restrict__ xhi, __half* __restrict__ xlo) {
    int row = blockIdx.x;
    int id  = ids[row];
    int t = threadIdx.x;
    float4 v = reinterpret_cast<const float4*>(emb + (long)id * EMBED)[t];
    reinterpret_cast<float4*>(x + (long)row * EMBED)[t] = v;
    __half h0, l0, h1, l1, h2, l2, h3, l3;
    hsplit(v.x, h0, l0); hsplit(v.y, h1, l1); hsplit(v.z, h2, l2); hsplit(v.w, h3, l3);
    __half2* dh = reinterpret_cast<__half2*>(xhi + (long)row * EMBED) + t * 2;
    __half2* dl = reinterpret_cast<__half2*>(xlo + (long)row * EMBED) + t * 2;
    dh[0] = __halves2half2(h0, h1); dh[1] = __halves2half2(h2, h3);
    dl[0] = __halves2half2(l0, l1); dl[1] = __halves2half2(l2, l3);
}

// ---------------------------------------------------------------------------
// Transpose fp32 [R,C] -> fp16 [C,R] (hi or hi+lo), batched via z
// ---------------------------------------------------------------------------
template<bool SPLIT>
__global__ void transpose_kernel(const float* __restrict__ in,
                                 __half* __restrict__ ohi, __half* __restrict__ olo,
                                 int R, int C, long sIn, long sOut) {
    __shared__ float t[32][33];
    long z = blockIdx.z;
    in  += z * sIn;
    ohi += z * sOut;
    if (SPLIT) olo += z * sOut;
    int c0 = blockIdx.x * 32, r0 = blockIdx.y * 32;
    int tx = threadIdx.x, ty = threadIdx.y;
    #pragma unroll
    for (int i = 0; i < 32; i += 8)
        t[ty + i][tx] = in[(long)(r0 + ty + i) * C + c0 + tx];
    __syncthreads();
    #pragma unroll
    for (int i = 0; i < 32; i += 8) {
        float v = t[tx][ty + i];
        long o = (long)(c0 + ty + i) * R + r0 + tx;
        if (SPLIT) {
            __half h, l; hsplit(v, h, l);
            ohi[o] = h; olo[o] = l;
        } else {
            ohi[o] = __float2half_rn(v);
        }
    }
}

// ---------------------------------------------------------------------------
// Softmax rows (fp32 in) -> fp16 hi/lo weights
// ---------------------------------------------------------------------------
__global__ __launch_bounds__(256)
void softmax_kernel(const float* __restrict__ scores,
                    __half* __restrict__ whi, __half* __restrict__ wlo) {
    __shared__ float red[256];
    const float* row = scores + (long)blockIdx.x * SEQ;
    __half* oh = whi + (long)blockIdx.x * SEQ;
    __half* ol = wlo + (long)blockIdx.x * SEQ;
    const int tid = threadIdx.x;

    float v[8];
    float lmax = -3.402823466e+38f;
    #pragma unroll
    for (int i = 0; i < 8; i++) { v[i] = row[tid + i * 256]; lmax = fmaxf(lmax, v[i]); }
    red[tid] = lmax; __syncthreads();
    #pragma unroll
    for (int s = 128; s > 0; s >>= 1) { if (tid < s) red[tid] = fmaxf(red[tid], red[tid + s]); __syncthreads(); }
    float m = red[0]; __syncthreads();

    float lsum = 0.f;
    #pragma unroll
    for (int i = 0; i < 8; i++) { v[i] = __expf(v[i] - m); lsum += v[i]; }
    red[tid] = lsum; __syncthreads();
    #pragma unroll
    for (int s = 128; s > 0; s >>= 1) { if (tid < s) red[tid] += red[tid + s]; __syncthreads(); }
    float inv = 1.f / red[0];
    #pragma unroll
    for (int i = 0; i < 8; i++) {
        float w = v[i] * inv;
        __half h, l; hsplit(w, h, l);
        oh[tid + i * 256] = h; ol[tid + i * 256] = l;
    }
}

// ---------------------------------------------------------------------------
// HMMA split-fp16 GEMM:  C[M,N] = A[M,K] * B[N,K]^T
// MODE=2: terms A0*B0 + A1*B0 (A split hi/lo, B single)
// MODE=3: terms A0*B0 + A1*B0 + A0*B1 (A and B both split)
// OUT=0: fp32 (+bias,+relu)   OUT=1: fp16 hi only   OUT=2: fp16 hi/lo
// CTA 128x128, BK=32, 8 warps (2x4), warp tile 64x32, 3-stage cp.async.
// ---------------------------------------------------------------------------
#define BMT 128
#define BNT 128
#define BKT 32
#define NSTAGE 3
#define TILE_BYTES 8192

template<int TPS>
__device__ __forceinline__ void load_chunk(uint32_t sbase, int st,
    const __half* __restrict__ gA0, const __half* __restrict__ gA1,
    const __half* __restrict__ gB0, const __half* __restrict__ gB1,
    int K, int k0, int tid)
{
    uint32_t s0 = sbase + (uint32_t)(st * TPS * TILE_BYTES);
    #pragma unroll
    for (int it = 0; it < 2; it++) {
        int idx = tid + it * 256;
        int r = idx >> 2, c = idx & 3;
        uint32_t so = (uint32_t)(r * 64 + ((c ^ (r & 3)) << 4));
        long go = (long)r * K + k0 + c * 8;
        CP_ASYNC16(s0 + 0 * TILE_BYTES + so, gA0 + go);
        CP_ASYNC16(s0 + 1 * TILE_BYTES + so, gA1 + go);
        CP_ASYNC16(s0 + 2 * TILE_BYTES + so, gB0 + go);
        if (TPS == 4) CP_ASYNC16(s0 + 3 * TILE_BYTES + so, gB1 + go);
    }
}

template<int MODE, int OUT, bool BIAS, bool RELU>
__global__ __launch_bounds__(256)
void hgemm(const __half* __restrict__ A0, const __half* __restrict__ A1,
           const __half* __restrict__ B0, const __half* __restrict__ B1,
           const float* __restrict__ bias,
           float* __restrict__ Cf, __half* __restrict__ Chi, __half* __restrict__ Clo,
           int M, int N, int K, long sA, long sB, long sC, int ntm)
{
    extern __shared__ char smem[];
    const uint32_t sbase = smem_u32(smem);
    const int tid  = threadIdx.x;
    const int wid  = tid >> 5, lane = tid & 31;
    const int wm   = wid & 1,  wn   = wid >> 1;
    constexpr int TPS = (MODE == 3) ? 4 : 3;

    int pm = blockIdx.x % ntm, pn = blockIdx.x / ntm;
    long m0 = (long)pm * BMT, n0 = (long)pn * BNT;
    long zb = blockIdx.z;
    const __half* gA0 = A0 + zb * sA + m0 * K;
    const __half* gA1 = A1 + zb * sA + m0 * K;
    const __half* gB0 = B0 + zb * sB + n0 * K;
    const __half* gB1 = (MODE == 3) ? (B1 + zb * sB + n0 * K) : gB0;

    float acc[4][4][4];
    #pragma unroll
    for (int i = 0; i < 4; i++)
        #pragma unroll
        for (int j = 0; j < 4; j++)
            #pragma unroll
            for (int k = 0; k < 4; k++) acc[i][j][k] = 0.f;

    load_chunk<TPS>(sbase, 0, gA0, gA1, gB0, gB1, K, 0, tid);   CP_COMMIT();
    load_chunk<TPS>(sbase, 1, gA0, gA1, gB0, gB1, K, BKT, tid); CP_COMMIT();

    const int nc = K / BKT;
    for (int c = 0; c < nc; c++) {
        CP_WAIT1();
        __syncthreads();
        if (c + 2 < nc)
            load_chunk<TPS>(sbase, (c + 2) % NSTAGE, gA0, gA1, gB0, gB1, K, (c + 2) * BKT, tid);
        CP_COMMIT();

        uint32_t s0 = sbase + (uint32_t)((c % NSTAGE) * TPS * TILE_BYTES);
        #pragma unroll
        for (int kb = 0; kb < BKT; kb += 16) {
            uint32_t a0f[4][4], a1f[4][4], b0f[2][4], b1f[2][4];
            int ar  = lane & 15;
            int akk = kb + ((lane >> 4) << 3);
            int br  = ((lane >> 4) << 3) + (lane & 7);
            int bkk = kb + (((lane >> 3) & 1) << 3);
            #pragma unroll
            for (int mt = 0; mt < 4; mt++) {
                int r = wm * 64 + mt * 16 + ar;
                uint32_t ad = s0 + (uint32_t)(r * 64 + ((((akk >> 3) ^ (r & 3))) << 4));
                ldsm4(a0f[mt], ad);
                ldsm4(a1f[mt], ad + TILE_BYTES);
            }
            #pragma unroll
            for (int nt = 0; nt < 2; nt++) {
                int r = wn * 32 + nt * 16 + br;
                uint32_t bd = s0 + 2 * TILE_BYTES
                            + (uint32_t)(r * 64 + ((((bkk >> 3) ^ (r & 3))) << 4));
                ldsm4(b0f[nt], bd);
                if (MODE == 3) ldsm4(b1f[nt], bd + TILE_BYTES);
            }
            #pragma unroll
            for (int mt = 0; mt < 4; mt++)
                #pragma unroll
                for (int n8 = 0; n8 < 4; n8++) {
                    const uint32_t* b = &b0f[n8 >> 1][(n8 & 1) * 2];
                    mma16816(acc[mt][n8], a0f[mt], b);
                    mma16816(acc[mt][n8], a1f[mt], b);
                    if (MODE == 3)
                        mma16816(acc[mt][n8], a0f[mt], &b1f[n8 >> 1][(n8 & 1) * 2]);
                }
        }
    }

    // ---- epilogue ----
    long zC = zb * sC;
    int rb = lane >> 2;
    int cb = (lane & 3) * 2;
    #pragma unroll
    for (int mt = 0; mt < 4; mt++) {
        #pragma unroll
        for (int n8 = 0; n8 < 4; n8++) {
            long col = n0 + wn * 32 + n8 * 8 + cb;
            float bv0 = 0.f, bv1 = 0.f;
            if (BIAS) { bv0 = bias[col]; bv1 = bias[col + 1]; }
            #pragma unroll
            for (int h = 0; h < 2; h++) {
                long row = m0 + wm * 64 + mt * 16 + rb + h * 8;
                float v0 = acc[mt][n8][h * 2 + 0] + bv0;
                float v1 = acc[mt][n8][h * 2 + 1] + bv1;
                if (RELU) { v0 = fmaxf(v0, 0.f); v1 = fmaxf(v1, 0.f); }
                long o = row * (long)N + col;
                if (OUT == 0) {
                    *reinterpret_cast<float2*>(Cf + zC + o) = make_float2(v0, v1);
                } else if (OUT == 1) {
                    *reinterpret_cast<__half2*>(Chi + zC + o) =
                        __halves2half2(__float2half_rn(v0), __float2half_rn(v1));
                } else {
                    __half h0, l0, h1, l1;
                    hsplit(v0, h0, l0); hsplit(v1, h1, l1);
                    *reinterpret_cast<__half2*>(Chi + zC + o) = __halves2half2(h0, h1);
                    *reinterpret_cast<__half2*>(Clo + zC + o) = __halves2half2(l0, l1);
                }
            }
        }
    }
}

// ---------------------------------------------------------------------------
// Wide single-term HMMA GEMM:  C[M,N] = A[M,K] * B[N,K]^T + bias  (fp32 out)
// CTA 128x256, BK=32, 8 warps (2x4), warp tile 64x64, 4-stage cp.async.
// Used for FFN2 (the 2.15 TF GEMM).
// ---------------------------------------------------------------------------
#define WNS 4                      // pipeline stages
#define W_ABYTES 8192              // 128 x 32 fp16
#define W_BBYTES 16384             // 256 x 32 fp16
#define W_STAGE  (W_ABYTES + W_BBYTES)

__device__ __forceinline__ void load_chunk_wide(uint32_t sbase, int st,
    const __half* __restrict__ gA, const __half* __restrict__ gB,
    int K, int k0, int tid)
{
    uint32_t s0 = sbase + (uint32_t)(st * W_STAGE);
    #pragma unroll
    for (int it = 0; it < 2; it++) {
        int idx = tid + it * 256;
        int r = idx >> 2, c = idx & 3;
        uint32_t so = (uint32_t)(r * 64 + ((c ^ (r & 3)) << 4));
        CP_ASYNC16(s0 + so, gA + (long)r * K + k0 + c * 8);
    }
    #pragma unroll
    for (int it = 0; it < 4; it++) {
        int idx = tid + it * 256;
        int r = idx >> 2, c = idx & 3;
        uint32_t so = (uint32_t)(r * 64 + ((c ^ (r & 3)) << 4));
        CP_ASYNC16(s0 + W_ABYTES + so, gB + (long)r * K + k0 + c * 8);
    }
}

template<bool BIAS>
__global__ __launch_bounds__(256)
void hgemm_wide(const __half* __restrict__ A0, const __half* __restrict__ B0,
                const float* __restrict__ bias, float* __restrict__ Cf,
                int M, int N, int K, int ntm)
{
    extern __shared__ char smem[];
    const uint32_t sbase = smem_u32(smem);
    const int tid  = threadIdx.x;
    const int wid  = tid >> 5, lane = tid & 31;
    const int wm   = wid & 1,  wn   = wid >> 1;

    int pm = blockIdx.x % ntm, pn = blockIdx.x / ntm;
    long m0 = (long)pm * 128, n0 = (long)pn * 256;
    const __half* gA = A0 + m0 * K;
    const __half* gB = B0 + n0 * K;

    float acc[4][8][4];
    #pragma unroll
    for (int i = 0; i < 4; i++)
        #pragma unroll
        for (int j = 0; j < 8; j++)
            #pragma unroll
            for (int k = 0; k < 4; k++) acc[i][j][k] = 0.f;

    load_chunk_wide(sbase, 0, gA, gB, K, 0, tid);      CP_COMMIT();
    load_chunk_wide(sbase, 1, gA, gB, K, BKT, tid);    CP_COMMIT();
    load_chunk_wide(sbase, 2, gA, gB, K, 2 * BKT, tid);CP_COMMIT();

    const int nc = K / BKT;
    for (int c = 0; c < nc; c++) {
        CP_WAIT2();
        __syncthreads();
        if (c + 3 < nc)
            load_chunk_wide(sbase, (c + 3) % WNS, gA, gB, K, (c + 3) * BKT, tid);
        CP_COMMIT();

        uint32_t s0 = sbase + (uint32_t)((c % WNS) * W_STAGE);
        #pragma unroll
        for (int kb = 0; kb < BKT; kb += 16) {
            uint32_t af[4][4], bf[4][4];
            int ar  = lane & 15;
            int akk = kb + ((lane >> 4) << 3);
            int br  = ((lane >> 4) << 3) + (lane & 7);
            int bkk = kb + (((lane >> 3) & 1) << 3);
            #pragma unroll
            for (int mt = 0; mt < 4; mt++) {
                int r = wm * 64 + mt * 16 + ar;
                ldsm4(af[mt], s0 + (uint32_t)(r * 64 + ((((akk >> 3) ^ (r & 3))) << 4)));
            }
            #pragma unroll
            for (int nt = 0; nt < 4; nt++) {
                int r = wn * 64 + nt * 16 + br;
                ldsm4(bf[nt], s0 + W_ABYTES
                              + (uint32_t)(r * 64 + ((((bkk >> 3) ^ (r & 3))) << 4)));
            }
            #pragma unroll
            for (int mt = 0; mt < 4; mt++)
                #pragma unroll
                for (int n8 = 0; n8 < 8; n8++)
                    mma16816(acc[mt][n8], af[mt], &bf[n8 >> 1][(n8 & 1) * 2]);
        }
    }

    // ---- epilogue ----
    int rb = lane >> 2;
    int cb = (lane & 3) * 2;
    #pragma unroll
    for (int mt = 0; mt < 4; mt++) {
        #pragma unroll
        for (int n8 = 0; n8 < 8; n8++) {
            long col = n0 + wn * 64 + n8 * 8 + cb;
            float bv0 = 0.f, bv1 = 0.f;
            if (BIAS) { bv0 = bias[col]; bv1 = bias[col + 1]; }
            #pragma unroll
            for (int h = 0; h < 2; h++) {
                long row = m0 + wm * 64 + mt * 16 + rb + h * 8;
                *reinterpret_cast<float2*>(Cf + row * (long)N + col) =
                    make_float2(acc[mt][n8][h * 2 + 0] + bv0,
                                acc[mt][n8][h * 2 + 1] + bv1);
            }
        }
    }
}

// ---------------------------------------------------------------------------
// Launch
// ---------------------------------------------------------------------------
extern "C" void kernel_launch(void* const* d_in, const int* in_sizes, int n_in,
                              void* d_out, int out_size) {
    const int*   ids = (const int*)  d_in[0];
    const float* emb = (const float*)d_in[1];
    const float* W1  = (const float*)d_in[2];
    const float* b1  = (const float*)d_in[3];
    const float* W2  = (const float*)d_in[4];
    const float* b2  = (const float*)d_in[5];
    float* out = (float*)d_out;

    float *x, *scores;
    __half *xhi, *xlo, *xThi, *xTlo, *whi, *wlo, *athi, *atlo, *hdhi, *w1t, *w2t;
    cudaGetSymbolAddress((void**)&x,      g_x);
    cudaGetSymbolAddress((void**)&scores, g_scores);
    cudaGetSymbolAddress((void**)&xhi,    g_xhi);
    cudaGetSymbolAddress((void**)&xlo,    g_xlo);
    cudaGetSymbolAddress((void**)&xThi,   g_xThi);
    cudaGetSymbolAddress((void**)&xTlo,   g_xTlo);
    cudaGetSymbolAddress((void**)&whi,    g_whi);
    cudaGetSymbolAddress((void**)&wlo,    g_wlo);
    cudaGetSymbolAddress((void**)&athi,   g_atthi);
    cudaGetSymbolAddress((void**)&atlo,   g_attlo);
    cudaGetSymbolAddress((void**)&hdhi,   g_hidhi);
    cudaGetSymbolAddress((void**)&w1t,    g_W1t);
    cudaGetSymbolAddress((void**)&w2t,    g_W2t);

    const int SM3 = 4 * NSTAGE * TILE_BYTES;  // 98304
    const int SM2 = 3 * NSTAGE * TILE_BYTES;  // 73728
    const int SMW = WNS * W_STAGE;            // 98304
    cudaFuncSetAttribute(hgemm<3, 0, false, false>, cudaFuncAttributeMaxDynamicSharedMemorySize, SM3);
    cudaFuncSetAttribute(hgemm<3, 2, false, false>, cudaFuncAttributeMaxDynamicSharedMemorySize, SM3);
    cudaFuncSetAttribute(hgemm<2, 1, true,  true >, cudaFuncAttributeMaxDynamicSharedMemorySize, SM2);
    cudaFuncSetAttribute(hgemm_wide<true>, cudaFuncAttributeMaxDynamicSharedMemorySize, SMW);

    // 1) embedding -> x fp32, x hi/lo fp16
    embed_kernel<<<BATCH * SEQ, 256>>>(ids, emb, x, xhi, xlo);

    // 2) xT hi/lo ([S,E] -> [E,S] per batch)
    {
        dim3 grid(EMBED / 32, SEQ / 32, BATCH);
        transpose_kernel<true><<<grid, dim3(32, 8)>>>(x, xThi, xTlo, SEQ, EMBED,
                                                      (long)SEQ * EMBED, (long)EMBED * SEQ);
    }
    // 3) W1t single fp16 ([E,H] -> [H,E])
    {
        dim3 grid(HID / 32, EMBED / 32, 1);
        transpose_kernel<false><<<grid, dim3(32, 8)>>>(W1, w1t, nullptr, EMBED, HID, 0, 0);
    }
    // 4) W2t single fp16 ([H,V] -> [V,H])
    {
        dim3 grid(VOCAB / 32, HID / 32, 1);
        transpose_kernel<false><<<grid, dim3(32, 8)>>>(W2, w2t, nullptr, HID, VOCAB, 0, 0);
    }

    // 5) scores = x @ x^T   (3-term, fp32 out)  M=N=2048 K=1024
    {
        dim3 grid((SEQ / BMT) * (SEQ / BNT), 1, BATCH);
        hgemm<3, 0, false, false><<<grid, 256, SM3>>>(
            xhi, xlo, xhi, xlo, nullptr, scores, nullptr, nullptr,
            SEQ, SEQ, EMBED, (long)SEQ * EMBED, (long)SEQ * EMBED, (long)SEQ * SEQ,
            SEQ / BMT);
    }

    // 6) softmax -> w hi/lo
    softmax_kernel<<<BATCH * SEQ, 256>>>(scores, whi, wlo);

    // 7) attended = w @ x   (3-term, fp16 hi/lo out)  M=2048 N=1024 K=2048
    {
        dim3 grid((SEQ / BMT) * (EMBED / BNT), 1, BATCH);
        hgemm<3, 2, false, false><<<grid, 256, SM3>>>(
            whi, wlo, xThi, xTlo, nullptr, nullptr, athi, atlo,
            SEQ, EMBED, SEQ, (long)SEQ * SEQ, (long)EMBED * SEQ, (long)SEQ * EMBED,
            SEQ / BMT);
    }

    // 8) hidden = relu(att @ W1 + b1)  (2-term A-split, fp16 hi out)  M=8192 N=4096 K=1024
    {
        dim3 grid(((BATCH * SEQ) / BMT) * (HID / BNT), 1, 1);
        hgemm<2, 1, true, true><<<grid, 256, SM2>>>(
            athi, atlo, w1t, nullptr, b1, nullptr, hdhi, nullptr,
            BATCH * SEQ, HID, EMBED, 0, 0, 0,
            (BATCH * SEQ) / BMT);
    }

    // 9) logits = hidden @ W2 + b2  (1-term wide, fp32 out)  M=8192 N=32000 K=4096
    {
        dim3 grid(((BATCH * SEQ) / 128) * (VOCAB / 256), 1, 1);
        hgemm_wide<true><<<grid, 256, SMW>>>(
            hdhi, w2t, b2, out, BATCH * SEQ, VOCAB, HID, (BATCH * SEQ) / 128);
    }
}

// round 6
// speedup vs baseline: 7.8345x; 1.3117x over previous
#include <cuda_runtime.h>
#include <cuda_fp16.h>
#include <cstdint>

// Problem dims
#define BATCH 4
#define SEQ   2048
#define EMBED 1024
#define HID   4096
#define VOCAB 32000

// ---------------------------------------------------------------------------
// PTX helpers (plain sm_103-legal: cp.async / ldmatrix / mma.sync only)
// ---------------------------------------------------------------------------
__device__ __forceinline__ uint32_t smem_u32(const void* p) {
    uint32_t a;
    asm("{ .reg .u64 t; cvta.to.shared.u64 t, %1; cvt.u32.u64 %0, t; }" : "=r"(a) : "l"(p));
    return a;
}
#define CP_ASYNC16(s, g) \
    asm volatile("cp.async.cg.shared.global [%0], [%1], 16;\n" :: "r"(s), "l"(g))
#define CP_COMMIT() asm volatile("cp.async.commit_group;\n" ::: "memory")
#define CP_WAIT1()  asm volatile("cp.async.wait_group 1;\n" ::: "memory")
#define CP_WAIT2()  asm volatile("cp.async.wait_group 2;\n" ::: "memory")

__device__ __forceinline__ void ldsm4(uint32_t* r, uint32_t a) {
    asm volatile("ldmatrix.sync.aligned.m8n8.x4.shared.b16 {%0,%1,%2,%3}, [%4];"
        : "=r"(r[0]), "=r"(r[1]), "=r"(r[2]), "=r"(r[3]) : "r"(a));
}
__device__ __forceinline__ void mma16816(float* c, const uint32_t* a, const uint32_t* b) {
    asm volatile(
        "mma.sync.aligned.m16n8k16.row.col.f32.f16.f16.f32 "
        "{%0,%1,%2,%3}, {%4,%5,%6,%7}, {%8,%9}, {%0,%1,%2,%3};"
        : "+f"(c[0]), "+f"(c[1]), "+f"(c[2]), "+f"(c[3])
        : "r"(a[0]), "r"(a[1]), "r"(a[2]), "r"(a[3]), "r"(b[0]), "r"(b[1]));
}

// 128B-row SW128 swizzle: row r, 16B-chunk q (0..7) -> byte offset in tile
#define SWZ(r, q) ((uint32_t)((r) * 128 + ((((q) ^ ((r) & 7))) << 4)))

// fp16 hi/lo split (hi+lo covers ~22 mantissa bits of the fp32 value)
__device__ __forceinline__ void hsplit(float v, __half& h, __half& l) {
    h = __float2half_rn(v);
    l = __float2half_rn(v - __half2float(h));
}

// ---------------------------------------------------------------------------
// Scratch (device globals)
// ---------------------------------------------------------------------------
__device__ float  g_x     [BATCH * SEQ * EMBED];
__device__ __half g_xhi   [BATCH * SEQ * EMBED];
__device__ __half g_xlo   [BATCH * SEQ * EMBED];
__device__ __half g_xThi  [BATCH * EMBED * SEQ];
__device__ __half g_xTlo  [BATCH * EMBED * SEQ];
__device__ float  g_scores[BATCH * SEQ * SEQ];
__device__ __half g_whi   [BATCH * SEQ * SEQ];
__device__ __half g_wlo   [BATCH * SEQ * SEQ];
__device__ __half g_atthi [BATCH * SEQ * EMBED];
__device__ __half g_attlo [BATCH * SEQ * EMBED];
__device__ __half g_hidhi [BATCH * SEQ * HID];
__device__ __half g_W1t   [HID * EMBED];
__device__ __half g_W2t   [(size_t)VOCAB * HID];

// ---------------------------------------------------------------------------
// Embedding gather: x fp32 + fp16 hi/lo
// ---------------------------------------------------------------------------
__global__ void embed_kernel(const int* __restrict__ ids, const float* __restrict__ emb,
                             float* __restrict__ x,
                             __half* __restrict__ xhi, __half* __restrict__ xlo) {
    int row = blockIdx.x;
    int id  = ids[row];
    int t = threadIdx.x;
    float4 v = reinterpret_cast<const float4*>(emb + (long)id * EMBED)[t];
    reinterpret_cast<float4*>(x + (long)row * EMBED)[t] = v;
    __half h0, l0, h1, l1, h2, l2, h3, l3;
    hsplit(v.x, h0, l0); hsplit(v.y, h1, l1); hsplit(v.z, h2, l2); hsplit(v.w, h3, l3);
    __half2* dh = reinterpret_cast<__half2*>(xhi + (long)row * EMBED) + t * 2;
    __half2* dl = reinterpret_cast<__half2*>(xlo + (long)row * EMBED) + t * 2;
    dh[0] = __halves2half2(h0, h1); dh[1] = __halves2half2(h2, h3);
    dl[0] = __halves2half2(l0, l1); dl[1] = __halves2half2(l2, l3);
}

// ---------------------------------------------------------------------------
// Transpose fp32 [R,C] -> fp16 [C,R] (hi or hi+lo), batched via z
// ---------------------------------------------------------------------------
template<bool SPLIT>
__global__ void transpose_kernel(const float* __restrict__ in,
                                 __half* __restrict__ ohi, __half* __restrict__ olo,
                                 int R, int C, long sIn, long sOut) {
    __shared__ float t[32][33];
    long z = blockIdx.z;
    in  += z * sIn;
    ohi += z * sOut;
    if (SPLIT) olo += z * sOut;
    int c0 = blockIdx.x * 32, r0 = blockIdx.y * 32;
    int tx = threadIdx.x, ty = threadIdx.y;
    #pragma unroll
    for (int i = 0; i < 32; i += 8)
        t[ty + i][tx] = in[(long)(r0 + ty + i) * C + c0 + tx];
    __syncthreads();
    #pragma unroll
    for (int i = 0; i < 32; i += 8) {
        float v = t[tx][ty + i];
        long o = (long)(c0 + ty + i) * R + r0 + tx;
        if (SPLIT) {
            __half h, l; hsplit(v, h, l);
            ohi[o] = h; olo[o] = l;
        } else {
            ohi[o] = __float2half_rn(v);
        }
    }
}

// ---------------------------------------------------------------------------
// Softmax rows (fp32 in) -> fp16 hi/lo weights
// ---------------------------------------------------------------------------
__global__ __launch_bounds__(256)
void softmax_kernel(const float* __restrict__ scores,
                    __half* __restrict__ whi, __half* __restrict__ wlo) {
    __shared__ float red[256];
    const float* row = scores + (long)blockIdx.x * SEQ;
    __half* oh = whi + (long)blockIdx.x * SEQ;
    __half* ol = wlo + (long)blockIdx.x * SEQ;
    const int tid = threadIdx.x;

    float v[8];
    float lmax = -3.402823466e+38f;
    #pragma unroll
    for (int i = 0; i < 8; i++) { v[i] = row[tid + i * 256]; lmax = fmaxf(lmax, v[i]); }
    red[tid] = lmax; __syncthreads();
    #pragma unroll
    for (int s = 128; s > 0; s >>= 1) { if (tid < s) red[tid] = fmaxf(red[tid], red[tid + s]); __syncthreads(); }
    float m = red[0]; __syncthreads();

    float lsum = 0.f;
    #pragma unroll
    for (int i = 0; i < 8; i++) { v[i] = __expf(v[i] - m); lsum += v[i]; }
    red[tid] = lsum; __syncthreads();
    #pragma unroll
    for (int s = 128; s > 0; s >>= 1) { if (tid < s) red[tid] += red[tid + s]; __syncthreads(); }
    float inv = 1.f / red[0];
    #pragma unroll
    for (int i = 0; i < 8; i++) {
        float w = v[i] * inv;
        __half h, l; hsplit(w, h, l);
        oh[tid + i * 256] = h; ol[tid + i * 256] = l;
    }
}

// ---------------------------------------------------------------------------
// HMMA split-fp16 GEMM:  C[M,N] = A[M,K] * B[N,K]^T
// MODE=2: terms A0*B0 + A1*B0 (A split hi/lo, B single)
// MODE=3: terms A0*B0 + A1*B0 + A0*B1 (A and B both split)
// OUT=0: fp32 (+bias,+relu)   OUT=1: fp16 hi only   OUT=2: fp16 hi/lo
// CTA 128x128, BK=64 (128B rows, conflict-free SW128), 8 warps, 3 stages.
// ---------------------------------------------------------------------------
#define BMT 128
#define BNT 128
#define BKT 64
#define NSTAGE 3
#define TILE_BYTES 16384    // 128 rows x 128 B

template<int TPS>
__device__ __forceinline__ void load_chunk(uint32_t sbase, int st,
    const __half* __restrict__ gA0, const __half* __restrict__ gA1,
    const __half* __restrict__ gB0, const __half* __restrict__ gB1,
    int K, int k0, int tid)
{
    uint32_t s0 = sbase + (uint32_t)(st * TPS * TILE_BYTES);
    #pragma unroll
    for (int it = 0; it < 4; it++) {
        int idx = tid + it * 256;
        int r = idx >> 3, c = idx & 7;
        uint32_t so = SWZ(r, c);
        long go = (long)r * K + k0 + c * 8;
        CP_ASYNC16(s0 + 0 * TILE_BYTES + so, gA0 + go);
        CP_ASYNC16(s0 + 1 * TILE_BYTES + so, gA1 + go);
        CP_ASYNC16(s0 + 2 * TILE_BYTES + so, gB0 + go);
        if (TPS == 4) CP_ASYNC16(s0 + 3 * TILE_BYTES + so, gB1 + go);
    }
}

template<int MODE, int OUT, bool BIAS, bool RELU>
__global__ __launch_bounds__(256)
void hgemm(const __half* __restrict__ A0, const __half* __restrict__ A1,
           const __half* __restrict__ B0, const __half* __restrict__ B1,
           const float* __restrict__ bias,
           float* __restrict__ Cf, __half* __restrict__ Chi, __half* __restrict__ Clo,
           int M, int N, int K, long sA, long sB, long sC, int ntm)
{
    extern __shared__ char smem[];
    const uint32_t sbase = smem_u32(smem);
    const int tid  = threadIdx.x;
    const int wid  = tid >> 5, lane = tid & 31;
    const int wm   = wid & 1,  wn   = wid >> 1;
    constexpr int TPS = (MODE == 3) ? 4 : 3;

    int pm = blockIdx.x % ntm, pn = blockIdx.x / ntm;
    long m0 = (long)pm * BMT, n0 = (long)pn * BNT;
    long zb = blockIdx.z;
    const __half* gA0 = A0 + zb * sA + m0 * K;
    const __half* gA1 = A1 + zb * sA + m0 * K;
    const __half* gB0 = B0 + zb * sB + n0 * K;
    const __half* gB1 = (MODE == 3) ? (B1 + zb * sB + n0 * K) : gB0;

    float acc[4][4][4];
    #pragma unroll
    for (int i = 0; i < 4; i++)
        #pragma unroll
        for (int j = 0; j < 4; j++)
            #pragma unroll
            for (int k = 0; k < 4; k++) acc[i][j][k] = 0.f;

    load_chunk<TPS>(sbase, 0, gA0, gA1, gB0, gB1, K, 0, tid);   CP_COMMIT();
    load_chunk<TPS>(sbase, 1, gA0, gA1, gB0, gB1, K, BKT, tid); CP_COMMIT();

    const int nc = K / BKT;
    for (int c = 0; c < nc; c++) {
        CP_WAIT1();
        __syncthreads();
        if (c + 2 < nc)
            load_chunk<TPS>(sbase, (c + 2) % NSTAGE, gA0, gA1, gB0, gB1, K, (c + 2) * BKT, tid);
        CP_COMMIT();

        uint32_t s0 = sbase + (uint32_t)((c % NSTAGE) * TPS * TILE_BYTES);
        #pragma unroll
        for (int kb = 0; kb < BKT; kb += 16) {
            uint32_t a0f[4][4], a1f[4][4], b0f[2][4], b1f[2][4];
            int ar  = lane & 15;
            int aq  = (kb + ((lane >> 4) << 3)) >> 3;
            int br  = ((lane >> 4) << 3) + (lane & 7);
            int bq  = (kb + (((lane >> 3) & 1) << 3)) >> 3;
            #pragma unroll
            for (int mt = 0; mt < 4; mt++) {
                int r = wm * 64 + mt * 16 + ar;
                uint32_t ad = s0 + SWZ(r, aq);
                ldsm4(a0f[mt], ad);
                ldsm4(a1f[mt], ad + TILE_BYTES);
            }
            #pragma unroll
            for (int nt = 0; nt < 2; nt++) {
                int r = wn * 32 + nt * 16 + br;
                uint32_t bd = s0 + 2 * TILE_BYTES + SWZ(r, bq);
                ldsm4(b0f[nt], bd);
                if (MODE == 3) ldsm4(b1f[nt], bd + TILE_BYTES);
            }
            #pragma unroll
            for (int mt = 0; mt < 4; mt++)
                #pragma unroll
                for (int n8 = 0; n8 < 4; n8++) {
                    const uint32_t* b = &b0f[n8 >> 1][(n8 & 1) * 2];
                    mma16816(acc[mt][n8], a0f[mt], b);
                    mma16816(acc[mt][n8], a1f[mt], b);
                    if (MODE == 3)
                        mma16816(acc[mt][n8], a0f[mt], &b1f[n8 >> 1][(n8 & 1) * 2]);
                }
        }
    }

    // ---- epilogue ----
    long zC = zb * sC;
    int rb = lane >> 2;
    int cb = (lane & 3) * 2;
    #pragma unroll
    for (int mt = 0; mt < 4; mt++) {
        #pragma unroll
        for (int n8 = 0; n8 < 4; n8++) {
            long col = n0 + wn * 32 + n8 * 8 + cb;
            float bv0 = 0.f, bv1 = 0.f;
            if (BIAS) { bv0 = bias[col]; bv1 = bias[col + 1]; }
            #pragma unroll
            for (int h = 0; h < 2; h++) {
                long row = m0 + wm * 64 + mt * 16 + rb + h * 8;
                float v0 = acc[mt][n8][h * 2 + 0] + bv0;
                float v1 = acc[mt][n8][h * 2 + 1] + bv1;
                if (RELU) { v0 = fmaxf(v0, 0.f); v1 = fmaxf(v1, 0.f); }
                long o = row * (long)N + col;
                if (OUT == 0) {
                    *reinterpret_cast<float2*>(Cf + zC + o) = make_float2(v0, v1);
                } else if (OUT == 1) {
                    *reinterpret_cast<__half2*>(Chi + zC + o) =
                        __halves2half2(__float2half_rn(v0), __float2half_rn(v1));
                } else {
                    __half h0, l0, h1, l1;
                    hsplit(v0, h0, l0); hsplit(v1, h1, l1);
                    *reinterpret_cast<__half2*>(Chi + zC + o) = __halves2half2(h0, h1);
                    *reinterpret_cast<__half2*>(Clo + zC + o) = __halves2half2(l0, l1);
                }
            }
        }
    }
}

// ---------------------------------------------------------------------------
// Wide single-term HMMA GEMM:  C[M,N] = A[M,K] * B[N,K]^T + bias  (fp32 out)
// CTA 128x256, BK=64 (128B rows, SW128), 8 warps (64x64 warp tile), 4 stages.
// ---------------------------------------------------------------------------
#define WNS 4
#define W_ABYTES 16384             // 128 x 128 B
#define W_BBYTES 32768             // 256 x 128 B
#define W_STAGE  (W_ABYTES + W_BBYTES)

__device__ __forceinline__ void load_chunk_wide(uint32_t sbase, int st,
    const __half* __restrict__ gA, const __half* __restrict__ gB,
    int K, int k0, int tid)
{
    uint32_t s0 = sbase + (uint32_t)(st * W_STAGE);
    #pragma unroll
    for (int it = 0; it < 4; it++) {
        int idx = tid + it * 256;
        int r = idx >> 3, c = idx & 7;
        CP_ASYNC16(s0 + SWZ(r, c), gA + (long)r * K + k0 + c * 8);
    }
    #pragma unroll
    for (int it = 0; it < 8; it++) {
        int idx = tid + it * 256;
        int r = idx >> 3, c = idx & 7;
        CP_ASYNC16(s0 + W_ABYTES + SWZ(r, c), gB + (long)r * K + k0 + c * 8);
    }
}

template<bool BIAS>
__global__ __launch_bounds__(256)
void hgemm_wide(const __half* __restrict__ A0, const __half* __restrict__ B0,
                const float* __restrict__ bias, float* __restrict__ Cf,
                int M, int N, int K, int ntm)
{
    extern __shared__ char smem[];
    const uint32_t sbase = smem_u32(smem);
    const int tid  = threadIdx.x;
    const int wid  = tid >> 5, lane = tid & 31;
    const int wm   = wid & 1,  wn   = wid >> 1;

    int pm = blockIdx.x % ntm, pn = blockIdx.x / ntm;
    long m0 = (long)pm * 128, n0 = (long)pn * 256;
    const __half* gA = A0 + m0 * K;
    const __half* gB = B0 + n0 * K;

    float acc[4][8][4];
    #pragma unroll
    for (int i = 0; i < 4; i++)
        #pragma unroll
        for (int j = 0; j < 8; j++)
            #pragma unroll
            for (int k = 0; k < 4; k++) acc[i][j][k] = 0.f;

    load_chunk_wide(sbase, 0, gA, gB, K, 0, tid);        CP_COMMIT();
    load_chunk_wide(sbase, 1, gA, gB, K, BKT, tid);      CP_COMMIT();
    load_chunk_wide(sbase, 2, gA, gB, K, 2 * BKT, tid);  CP_COMMIT();

    const int nc = K / BKT;
    for (int c = 0; c < nc; c++) {
        CP_WAIT2();
        __syncthreads();
        if (c + 3 < nc)
            load_chunk_wide(sbase, (c + 3) % WNS, gA, gB, K, (c + 3) * BKT, tid);
        CP_COMMIT();

        uint32_t s0 = sbase + (uint32_t)((c % WNS) * W_STAGE);
        #pragma unroll
        for (int kb = 0; kb < BKT; kb += 16) {
            uint32_t af[4][4], bf[4][4];
            int ar = lane & 15;
            int aq = (kb + ((lane >> 4) << 3)) >> 3;
            int br = ((lane >> 4) << 3) + (lane & 7);
            int bq = (kb + (((lane >> 3) & 1) << 3)) >> 3;
            #pragma unroll
            for (int mt = 0; mt < 4; mt++) {
                int r = wm * 64 + mt * 16 + ar;
                ldsm4(af[mt], s0 + SWZ(r, aq));
            }
            #pragma unroll
            for (int nt = 0; nt < 4; nt++) {
                int r = wn * 64 + nt * 16 + br;
                ldsm4(bf[nt], s0 + W_ABYTES + SWZ(r, bq));
            }
            #pragma unroll
            for (int mt = 0; mt < 4; mt++)
                #pragma unroll
                for (int n8 = 0; n8 < 8; n8++)
                    mma16816(acc[mt][n8], af[mt], &bf[n8 >> 1][(n8 & 1) * 2]);
        }
    }

    // ---- epilogue ----
    int rb = lane >> 2;
    int cb = (lane & 3) * 2;
    #pragma unroll
    for (int mt = 0; mt < 4; mt++) {
        #pragma unroll
        for (int n8 = 0; n8 < 8; n8++) {
            long col = n0 + wn * 64 + n8 * 8 + cb;
            float bv0 = 0.f, bv1 = 0.f;
            if (BIAS) { bv0 = bias[col]; bv1 = bias[col + 1]; }
            #pragma unroll
            for (int h = 0; h < 2; h++) {
                long row = m0 + wm * 64 + mt * 16 + rb + h * 8;
                *reinterpret_cast<float2*>(Cf + row * (long)N + col) =
                    make_float2(acc[mt][n8][h * 2 + 0] + bv0,
                                acc[mt][n8][h * 2 + 1] + bv1);
            }
        }
    }
}

// ---------------------------------------------------------------------------
// Launch
// ---------------------------------------------------------------------------
extern "C" void kernel_launch(void* const* d_in, const int* in_sizes, int n_in,
                              void* d_out, int out_size) {
    const int*   ids = (const int*)  d_in[0];
    const float* emb = (const float*)d_in[1];
    const float* W1  = (const float*)d_in[2];
    const float* b1  = (const float*)d_in[3];
    const float* W2  = (const float*)d_in[4];
    const float* b2  = (const float*)d_in[5];
    float* out = (float*)d_out;

    float *x, *scores;
    __half *xhi, *xlo, *xThi, *xTlo, *whi, *wlo, *athi, *atlo, *hdhi, *w1t, *w2t;
    cudaGetSymbolAddress((void**)&x,      g_x);
    cudaGetSymbolAddress((void**)&scores, g_scores);
    cudaGetSymbolAddress((void**)&xhi,    g_xhi);
    cudaGetSymbolAddress((void**)&xlo,    g_xlo);
    cudaGetSymbolAddress((void**)&xThi,   g_xThi);
    cudaGetSymbolAddress((void**)&xTlo,   g_xTlo);
    cudaGetSymbolAddress((void**)&whi,    g_whi);
    cudaGetSymbolAddress((void**)&wlo,    g_wlo);
    cudaGetSymbolAddress((void**)&athi,   g_atthi);
    cudaGetSymbolAddress((void**)&atlo,   g_attlo);
    cudaGetSymbolAddress((void**)&hdhi,   g_hidhi);
    cudaGetSymbolAddress((void**)&w1t,    g_W1t);
    cudaGetSymbolAddress((void**)&w2t,    g_W2t);

    const int SM3 = 4 * NSTAGE * TILE_BYTES;  // 196608
    const int SM2 = 3 * NSTAGE * TILE_BYTES;  // 147456
    const int SMW = WNS * W_STAGE;            // 196608
    cudaFuncSetAttribute(hgemm<3, 0, false, false>, cudaFuncAttributeMaxDynamicSharedMemorySize, SM3);
    cudaFuncSetAttribute(hgemm<3, 2, false, false>, cudaFuncAttributeMaxDynamicSharedMemorySize, SM3);
    cudaFuncSetAttribute(hgemm<2, 1, true,  true >, cudaFuncAttributeMaxDynamicSharedMemorySize, SM2);
    cudaFuncSetAttribute(hgemm_wide<true>, cudaFuncAttributeMaxDynamicSharedMemorySize, SMW);

    // 1) embedding -> x fp32, x hi/lo fp16
    embed_kernel<<<BATCH * SEQ, 256>>>(ids, emb, x, xhi, xlo);

    // 2) xT hi/lo ([S,E] -> [E,S] per batch)
    {
        dim3 grid(EMBED / 32, SEQ / 32, BATCH);
        transpose_kernel<true><<<grid, dim3(32, 8)>>>(x, xThi, xTlo, SEQ, EMBED,
                                                      (long)SEQ * EMBED, (long)EMBED * SEQ);
    }
    // 3) W1t single fp16 ([E,H] -> [H,E])
    {
        dim3 grid(HID / 32, EMBED / 32, 1);
        transpose_kernel<false><<<grid, dim3(32, 8)>>>(W1, w1t, nullptr, EMBED, HID, 0, 0);
    }
    // 4) W2t single fp16 ([H,V] -> [V,H])
    {
        dim3 grid(VOCAB / 32, HID / 32, 1);
        transpose_kernel<false><<<grid, dim3(32, 8)>>>(W2, w2t, nullptr, HID, VOCAB, 0, 0);
    }

    // 5) scores = x @ x^T   (3-term, fp32 out)  M=N=2048 K=1024
    {
        dim3 grid((SEQ / BMT) * (SEQ / BNT), 1, BATCH);
        hgemm<3, 0, false, false><<<grid, 256, SM3>>>(
            xhi, xlo, xhi, xlo, nullptr, scores, nullptr, nullptr,
            SEQ, SEQ, EMBED, (long)SEQ * EMBED, (long)SEQ * EMBED, (long)SEQ * SEQ,
            SEQ / BMT);
    }

    // 6) softmax -> w hi/lo
    softmax_kernel<<<BATCH * SEQ, 256>>>(scores, whi, wlo);

    // 7) attended = w @ x   (3-term, fp16 hi/lo out)  M=2048 N=1024 K=2048
    {
        dim3 grid((SEQ / BMT) * (EMBED / BNT), 1, BATCH);
        hgemm<3, 2, false, false><<<grid, 256, SM3>>>(
            whi, wlo, xThi, xTlo, nullptr, nullptr, athi, atlo,
            SEQ, EMBED, SEQ, (long)SEQ * SEQ, (long)EMBED * SEQ, (long)SEQ * EMBED,
            SEQ / BMT);
    }

    // 8) hidden = relu(att @ W1 + b1)  (2-term A-split, fp16 hi out)  M=8192 N=4096 K=1024
    {
        dim3 grid(((BATCH * SEQ) / BMT) * (HID / BNT), 1, 1);
        hgemm<2, 1, true, true><<<grid, 256, SM2>>>(
            athi, atlo, w1t, nullptr, b1, nullptr, hdhi, nullptr,
            BATCH * SEQ, HID, EMBED, 0, 0, 0,
            (BATCH * SEQ) / BMT);
    }

    // 9) logits = hidden @ W2 + b2  (1-term wide, fp32 out)  M=8192 N=32000 K=4096
    {
        dim3 grid(((BATCH * SEQ) / 128) * (VOCAB / 256), 1, 1);
        hgemm_wide<true><<<grid, 256, SMW>>>(
            hdhi, w2t, b2, out, BATCH * SEQ, VOCAB, HID, (BATCH * SEQ) / 128);
    }
}